// round 6
// baseline (speedup 1.0000x reference)
#include <cuda_runtime.h>
#include <cuda_bf16.h>
#include <cstdint>

#define BB 32
#define NN 64
#define FF 1280
#define HH 512
#define EE 512
#define VV 10000
#define TT 80
#define G4 2048

#define OFF_H   25600000ll
#define OFF_C   25616384ll
#define OFF_ATT 25632768ll

// ---------------- device state ----------------
__device__ float g_h[2][BB * HH];
__device__ float g_c[2][BB * HH];
__device__ float g_hq[BB * HH];
__device__ float g_gate[BB * FF];
__device__ float g_ctxg[BB * FF];
__device__ float g_scor[BB * NN];
__device__ float g_encproj[BB * NN * HH];
__device__ float g_gpart[6][BB * G4];
__device__ unsigned long long g_amax[BB];

// ---------------- helpers ----------------
__device__ __forceinline__ unsigned long long pk2(float lo, float hi) {
    unsigned long long r;
    asm("mov.b64 %0, {%1,%2};" : "=l"(r) : "f"(lo), "f"(hi));
    return r;
}
__device__ __forceinline__ void upk2(unsigned long long v, float& lo, float& hi) {
    asm("mov.b64 {%0,%1}, %2;" : "=f"(lo), "=f"(hi) : "l"(v));
}
__device__ __forceinline__ void fma2(unsigned long long& d, unsigned long long a,
                                     unsigned long long b) {
    asm("fma.rn.f32x2 %0, %1, %2, %0;" : "+l"(d) : "l"(a), "l"(b));
}
__device__ __forceinline__ float sigf(float x) { return 1.0f / (1.0f + expf(-x)); }
__device__ __forceinline__ unsigned mono32(float f) {
    unsigned u = __float_as_uint(f);
    return (u & 0x80000000u) ? ~u : (u | 0x80000000u);
}
__device__ __forceinline__ uint32_t s2u(const void* p) {
    return (uint32_t)__cvta_generic_to_shared(p);
}
__device__ __forceinline__ void cp16(uint32_t dst, const void* src) {
    asm volatile("cp.async.ca.shared.global [%0], [%1], 16;" :: "r"(dst), "l"(src));
}
__device__ __forceinline__ void cp_commit() {
    asm volatile("cp.async.commit_group;");
}
template <int n>
__device__ __forceinline__ void cp_wait() {
    asm volatile("cp.async.wait_group %0;" :: "n"(n));
}

// ---------------- GEMM v6 ----------------
// C[32, 64-col tile] = A[32,K] @ W[K,N].  256 threads (8 warps).
// warp w -> rows 4w..4w+3 ; lane -> cols (col0, col0+1), col0 = bcol + 2*lane.
// A staged once into smem as s_a[k*36 + row]  (one broadcast LDS.128 per k).
// W streamed via cp.async, double-buffered 64-k chunks (16KB each).
#define CHK 64
#define WBUF (CHK * 64)      // floats per W buffer
#define PAD 36

__device__ __forceinline__ void fill_w(const float* __restrict__ W, int ldw,
                                       int bcol, int N, int k0, float* s_wbuf)
{
    int tid = threadIdx.x;
    int kk = tid >> 4;             // 0..15
    int c4 = (tid & 15) * 4;       // 0..60
    int col = bcol + c4;
#pragma unroll
    for (int p = 0; p < 4; p++) {
        int k = k0 + kk + p * 16;
        if (col < N)
            cp16(s2u(s_wbuf + (kk + p * 16) * 64 + c4),
                 W + (size_t)k * ldw + col);
    }
    cp_commit();
}

template <int K, class AElem>
__device__ __forceinline__ void gemm_v6(AElem aelem, const float* __restrict__ W,
    int ldw, int N, int bcol, unsigned long long acc[4], float* s_dyn)
{
    const int tid = threadIdx.x;
    const int lane = tid & 31;
    const int w = tid >> 5;
    float* s_w = s_dyn;                  // 2 * WBUF floats
    float* s_a = s_dyn + 2 * WBUF;       // K*PAD floats
    constexpr int C = K / CHK;

    fill_w(W, ldw, bcol, N, 0, s_w);
    if (C > 1) fill_w(W, ldw, bcol, N, CHK, s_w + WBUF);

    // stage A: s_a[k*PAD + r]  (coalesced global reads, k fastest)
#pragma unroll 1
    for (int r = 0; r < 32; r++) {
#pragma unroll
        for (int j = 0; j < K / 256; j++)
            s_a[(j * 256 + tid) * PAD + r] = aelem(r, j * 256 + tid);
        if (K % 256) {
            int k = (K / 256) * 256 + tid;
            if (k < K) s_a[k * PAD + r] = aelem(r, k);
        }
    }

    const float* sa = s_a + 4 * w;
#pragma unroll 1
    for (int c = 0; c < C; c++) {
        if (c + 1 < C) cp_wait<1>(); else cp_wait<0>();
        __syncthreads();
        const float* sw = s_w + (c & 1) * WBUF + 2 * lane;
        const float* sac = sa + c * CHK * PAD;
#pragma unroll 16
        for (int kk = 0; kk < CHK; kk++) {
            float2 w2 = *(const float2*)(sw + kk * 64);
            float4 a4 = *(const float4*)(sac + kk * PAD);
            unsigned long long wp = pk2(w2.x, w2.y);
            fma2(acc[0], wp, pk2(a4.x, a4.x));
            fma2(acc[1], wp, pk2(a4.y, a4.y));
            fma2(acc[2], wp, pk2(a4.z, a4.z));
            fma2(acc[3], wp, pk2(a4.w, a4.w));
        }
        if (c + 2 < C) {
            __syncthreads();
            fill_w(W, ldw, bcol, N, (c + 2) * CHK, s_w + (c & 1) * WBUF);
        }
    }
}

// Epilogue: +bias, optional sigmoid, store (with N guard).
__device__ __forceinline__ void store_tile(unsigned long long acc[4],
    float* C, int ldc, int bcol, int N, const float* __restrict__ bias, int act)
{
    int lane = threadIdx.x & 31, w = threadIdx.x >> 5;
    int col0 = bcol + lane * 2;
    float b0 = 0.f, b1 = 0.f;
    if (bias) {
        if (col0 < N) b0 = bias[col0];
        if (col0 + 1 < N) b1 = bias[col0 + 1];
    }
#pragma unroll
    for (int r = 0; r < 4; r++) {
        int row = 4 * w + r;
        float a, b;
        upk2(acc[r], a, b);
        a += b0; b += b1;
        if (act == 1) { a = sigf(a); b = sigf(b); }
        if (col0 < N)     C[(size_t)row * ldc + col0] = a;
        if (col0 + 1 < N) C[(size_t)row * ldc + col0 + 1] = b;
    }
}

// ---------------- setup ----------------
__global__ void __launch_bounds__(256) k_encproj(const float* __restrict__ feat,
                                                 const float* __restrict__ W2,
                                                 const float* __restrict__ b2)
{
    extern __shared__ float s_dyn[];
    unsigned long long acc[4] = {0, 0, 0, 0};
    int bcol = blockIdx.x * 64;
    const float* A = feat + (size_t)blockIdx.y * 32 * FF;
    gemm_v6<FF>([&](int r, int k) { return A[(size_t)r * FF + k]; },
                W2, HH, HH, bcol, acc, s_dyn);
    store_tile(acc, g_encproj + (size_t)blockIdx.y * 32 * HH, HH, bcol, HH, b2, 0);
}

__global__ void __launch_bounds__(256) k_init(const float* __restrict__ feat,
                                              const float* __restrict__ Wh,
                                              const float* __restrict__ bh,
                                              const float* __restrict__ Wc,
                                              const float* __restrict__ bc)
{
    __shared__ float s_mean[FF];
    int b = blockIdx.x, tid = threadIdx.x;
    const float* fb = feat + (size_t)b * NN * FF;
    for (int f = tid; f < FF; f += 256) {
        float s = 0.f;
#pragma unroll 8
        for (int n = 0; n < NN; n++) s += fb[(size_t)n * FF + f];
        s_mean[f] = s * (1.0f / NN);
    }
    __syncthreads();
    for (int j = tid; j < HH; j += 256) {
        float ha = bh[j], ca = bc[j];
#pragma unroll 8
        for (int f = 0; f < FF; f++) {
            float m = s_mean[f];
            ha = fmaf(m, Wh[(size_t)f * HH + j], ha);
            ca = fmaf(m, Wc[(size_t)f * HH + j], ca);
        }
        g_h[0][b * HH + j] = ha;
        g_c[0][b * HH + j] = ca;
    }
    if (tid == 0) g_amax[b] = (unsigned long long)(0xFFFFFFFFu - 1u);  // SOS=1
}

// ---------------- per-step ----------------
// K_FUSEA(t): everything that depends only on h(t):
//   blocks 0..156   : logits(t-1) = h(t)@Wout + bout, dec out write + packed argmax (skip t=0)
//   blocks 157..164 : hq(t)   = h(t)@W1 + b1
//   blocks 165..184 : gate(t) = sig(h(t)@Wg + bg)
//   blocks 185..216 : gpart1(t) = h(t)@Whh
__global__ void __launch_bounds__(256) k_fuseA(int t,
    const float* __restrict__ Wout, const float* __restrict__ bout,
    const float* __restrict__ W1, const float* __restrict__ b1,
    const float* __restrict__ Wg, const float* __restrict__ bg,
    const float* __restrict__ Whh, float* __restrict__ out)
{
    extern __shared__ float s_dyn[];
    unsigned long long acc[4] = {0, 0, 0, 0};
    int p = t & 1;
    int bx = blockIdx.x;
    if (bx < 157) {
        if (t == 0) return;
        int bcol = bx * 64;
        gemm_v6<HH>([&](int r, int k) { return g_h[p][r * HH + k]; },
                    Wout, VV, VV, bcol, acc, s_dyn);
        int tt = t - 1;
        int lane = threadIdx.x & 31, w = threadIdx.x >> 5;
        int col0 = bcol + lane * 2;
        float b0 = (col0 < VV) ? bout[col0] : 0.f;
        float b1v = (col0 + 1 < VV) ? bout[col0 + 1] : 0.f;
#pragma unroll
        for (int r = 0; r < 4; r++) {
            int row = 4 * w + r;
            float a, b;
            upk2(acc[r], a, b);
            a += b0; b += b1v;
            unsigned long long best = 0ull;
            if (col0 < VV) {
                out[((size_t)row * TT + tt) * VV + col0] = a;
                best = ((unsigned long long)mono32(a) << 32) |
                       (0xFFFFFFFFu - (unsigned)col0);
            }
            if (col0 + 1 < VV) {
                out[((size_t)row * TT + tt) * VV + col0 + 1] = b;
                unsigned long long k1 = ((unsigned long long)mono32(b) << 32) |
                                        (0xFFFFFFFFu - (unsigned)(col0 + 1));
                if (k1 > best) best = k1;
            }
#pragma unroll
            for (int m = 16; m; m >>= 1) {
                unsigned long long o = __shfl_xor_sync(0xffffffffu, best, m);
                if (o > best) best = o;
            }
            if (lane == 0) atomicMax(&g_amax[row], best);
        }
    } else if (bx < 165) {
        int bcol = (bx - 157) * 64;
        gemm_v6<HH>([&](int r, int k) { return g_h[p][r * HH + k]; },
                    W1, HH, HH, bcol, acc, s_dyn);
        store_tile(acc, g_hq, HH, bcol, HH, b1, 0);
    } else if (bx < 185) {
        int bcol = (bx - 165) * 64;
        gemm_v6<HH>([&](int r, int k) { return g_h[p][r * HH + k]; },
                    Wg, FF, FF, bcol, acc, s_dyn);
        store_tile(acc, g_gate, FF, bcol, FF, bg, 1);
    } else {
        int bcol = (bx - 185) * 64;
        gemm_v6<HH>([&](int r, int k) { return g_h[p][r * HH + k]; },
                    Whh, G4, G4, bcol, acc, s_dyn);
        store_tile(acc, g_gpart[1], G4, bcol, G4, nullptr, 0);
    }
}

// K_FUSEB: blocks 0..31: gpart0 = emb[token]@WxTop + blstm ; blocks 32..63: scores
__global__ void __launch_bounds__(256) k_fuseB(const float* __restrict__ emb,
    const float* __restrict__ Wx, const float* __restrict__ blstm,
    const float* __restrict__ Va)
{
    extern __shared__ float s_dyn[];
    int bx = blockIdx.x;
    if (bx < 32) {
        __shared__ unsigned s_tok[32];
        if (threadIdx.x < 32)
            s_tok[threadIdx.x] =
                0xFFFFFFFFu - (unsigned)(g_amax[threadIdx.x] & 0xFFFFFFFFull);
        __syncthreads();
        unsigned long long acc[4] = {0, 0, 0, 0};
        int bcol = bx * 64;
        gemm_v6<EE>([&](int r, int k) { return emb[(size_t)s_tok[r] * EE + k]; },
                    Wx, G4, G4, bcol, acc, s_dyn);
        store_tile(acc, g_gpart[0], G4, bcol, G4, blstm, 0);
    } else {
        float* s_hq = s_dyn;
        float* s_va = s_dyn + HH;
        int b = bx - 32, tid = threadIdx.x;
        int w = tid >> 5, lane = tid & 31;
        for (int j = tid; j < HH; j += 256) { s_hq[j] = g_hq[b * HH + j]; s_va[j] = Va[j]; }
        __syncthreads();
#pragma unroll
        for (int q = 0; q < 8; q++) {
            int n = q * 8 + w;
            const float4* ep = (const float4*)(g_encproj + ((size_t)b * NN + n) * HH);
            float s = 0.f;
#pragma unroll
            for (int i = 0; i < 4; i++) {
                int e4 = lane + 32 * i;
                float4 v = ep[e4];
                float4 hq4 = *(const float4*)(s_hq + e4 * 4);
                float4 va4 = *(const float4*)(s_va + e4 * 4);
                s += fmaxf(v.x + hq4.x, 0.f) * va4.x;
                s += fmaxf(v.y + hq4.y, 0.f) * va4.y;
                s += fmaxf(v.z + hq4.z, 0.f) * va4.z;
                s += fmaxf(v.w + hq4.w, 0.f) * va4.w;
            }
#pragma unroll
            for (int m = 16; m; m >>= 1) s += __shfl_xor_sync(0xffffffffu, s, m);
            if (lane == 0) g_scor[b * NN + n] = s;
        }
    }
}

// K_CTX: redundant softmax per block + gated context chunk. grid (B, 10) x 128.
__global__ void __launch_bounds__(128) k_ctx(int t, const float* __restrict__ feat,
                                             float* __restrict__ out)
{
    __shared__ float s_w[NN], s_red[4];
    int b = blockIdx.x, fc = blockIdx.y, tid = threadIdx.x;
    int lane = tid & 31;
    float v = 0.f;
    if (tid < 64) v = g_scor[b * NN + tid];
    float m = v;
#pragma unroll
    for (int s = 16; s; s >>= 1) m = fmaxf(m, __shfl_xor_sync(0xffffffffu, m, s));
    if (tid < 64 && lane == 0) s_red[tid >> 5] = m;
    __syncthreads();
    if (tid < 64) {
        float e = __expf(v - fmaxf(s_red[0], s_red[1]));
        s_w[tid] = e;
        float sum = e;
#pragma unroll
        for (int s = 16; s; s >>= 1) sum += __shfl_xor_sync(0xffffffffu, sum, s);
        if (lane == 0) s_red[2 + (tid >> 5)] = sum;
    }
    __syncthreads();
    float inv = 1.0f / (s_red[2] + s_red[3]);
    int f = fc * 128 + tid;
    const float* fb = feat + (size_t)b * NN * FF + f;
    float a = 0.f;
#pragma unroll 16
    for (int n = 0; n < NN; n++) a += s_w[n] * fb[(size_t)n * FF];
    a *= inv;
    g_ctxg[b * FF + f] = a * g_gate[b * FF + f];
    if (fc == 0 && tid < 64)
        out[OFF_ATT + ((size_t)b * TT + t) * NN + tid] = s_w[tid] * inv;
}

// K_G2: gpart[2+ks] = ctxg(kslice) @ WxBot(kslice)   (4 K-slices of 320)
__global__ void __launch_bounds__(256) k_g2(const float* __restrict__ Wx)
{
    extern __shared__ float s_dyn[];
    unsigned long long acc[4] = {0, 0, 0, 0};
    int ks = blockIdx.y;
    int bcol = blockIdx.x * 64;
    const float* Wp = Wx + (size_t)(EE + ks * 320) * G4;
    int koff = ks * 320;
    gemm_v6<320>([&](int r, int k) { return g_ctxg[r * FF + koff + k]; },
                 Wp, G4, G4, bcol, acc, s_dyn);
    store_tile(acc, g_gpart[2 + ks], G4, bcol, G4, nullptr, 0);
}

// K_LSTM: sum 6 partials (fixed order), pointwise LSTM, write h/c. Reset argmax.
__global__ void __launch_bounds__(128) k_lstm(int p, int last, float* __restrict__ out)
{
    int b = blockIdx.x >> 2, ch = blockIdx.x & 3;
    int j = ch * 128 + threadIdx.x;
    float v[4];
#pragma unroll
    for (int g = 0; g < 4; g++) {
        float s = 0.f;
#pragma unroll
        for (int pt = 0; pt < 6; pt++) s += g_gpart[pt][b * G4 + g * HH + j];
        v[g] = s;
    }
    float c_old = g_c[p][b * HH + j];
    float c2 = sigf(v[1]) * c_old + sigf(v[0]) * tanhf(v[2]);
    float h2 = sigf(v[3]) * tanhf(c2);
    g_c[p ^ 1][b * HH + j] = c2;
    g_h[p ^ 1][b * HH + j] = h2;
    if (last) {
        out[OFF_H + b * HH + j] = h2;
        out[OFF_C + b * HH + j] = c2;
    }
    if (ch == 0 && threadIdx.x == 0) g_amax[b] = 0ull;
}

// ---------------- launch ----------------
extern "C" void kernel_launch(void* const* d_in, const int* in_sizes, int n_in,
                              void* d_out, int out_size)
{
    int off = (n_in >= 21) ? 1 : 0;
    const float* feat  = (const float*)d_in[0];
    const float* emb   = (const float*)d_in[2 + off];
    const float* W1    = (const float*)d_in[3 + off];
    const float* b1    = (const float*)d_in[4 + off];
    const float* W2    = (const float*)d_in[5 + off];
    const float* b2    = (const float*)d_in[6 + off];
    const float* Va    = (const float*)d_in[7 + off];
    const float* Wh    = (const float*)d_in[9 + off];
    const float* bh    = (const float*)d_in[10 + off];
    const float* Wc    = (const float*)d_in[11 + off];
    const float* bc    = (const float*)d_in[12 + off];
    const float* Wg    = (const float*)d_in[13 + off];
    const float* bg    = (const float*)d_in[14 + off];
    const float* Wx    = (const float*)d_in[15 + off];
    const float* Whh   = (const float*)d_in[16 + off];
    const float* blstm = (const float*)d_in[17 + off];
    const float* Wout  = (const float*)d_in[18 + off];
    const float* bout  = (const float*)d_in[19 + off];
    float* out = (float*)d_out;

    const int SMW    = 2 * WBUF * 4;                 // 32768
    const int SM512  = SMW + HH * PAD * 4;           // 106496
    const int SM320  = SMW + 320 * PAD * 4;          // 78848
    const int SM1280 = SMW + FF * PAD * 4;           // 217088
    cudaFuncSetAttribute(k_fuseA, cudaFuncAttributeMaxDynamicSharedMemorySize, SM512);
    cudaFuncSetAttribute(k_fuseB, cudaFuncAttributeMaxDynamicSharedMemorySize, SM512);
    cudaFuncSetAttribute(k_g2, cudaFuncAttributeMaxDynamicSharedMemorySize, SM320);
    cudaFuncSetAttribute(k_encproj, cudaFuncAttributeMaxDynamicSharedMemorySize, SM1280);

    k_init<<<BB, 256>>>(feat, Wh, bh, Wc, bc);
    k_encproj<<<dim3(HH / 64, (BB * NN) / 32), 256, SM1280>>>(feat, W2, b2);

    for (int t = 0; t < TT; t++) {
        k_fuseA<<<217, 256, SM512>>>(t, Wout, bout, W1, b1, Wg, bg, Whh, out);
        k_fuseB<<<64, 256, SM512>>>(emb, Wx, blstm, Va);
        k_ctx<<<dim3(BB, 10), 128>>>(t, feat, out);
        k_g2<<<dim3(G4 / 64, 4), 256, SM320>>>(Wx);
        k_lstm<<<BB * 4, 128>>>(t & 1, (t == TT - 1) ? 1 : 0, out);
    }
    // final logits for t=79 (h(80) is in g_h[80&1]); h-gemm side effects unused
    k_fuseA<<<217, 256, SM512>>>(TT, Wout, bout, W1, b1, Wg, bg, Whh, out);
}

// round 7
// speedup vs baseline: 1.3512x; 1.3512x over previous
#include <cuda_runtime.h>
#include <cuda_bf16.h>
#include <cstdint>

#define BB 32
#define NN 64
#define FF 1280
#define HH 512
#define EE 512
#define VV 10000
#define TT 80
#define G4 2048

#define OFF_H   25600000ll
#define OFF_C   25616384ll
#define OFF_ATT 25632768ll

// ---------------- device state ----------------
__device__ float g_h[2][BB * HH];
__device__ float g_c[2][BB * HH];
__device__ float g_hq[BB * HH];
__device__ float g_gate[BB * FF];
__device__ float g_ctxg[BB * FF];
__device__ float g_scor[BB * NN];
__device__ float g_encproj[BB * NN * HH];
__device__ float g_gpart[6][BB * G4];
__device__ unsigned long long g_amax[BB];
__device__ unsigned g_cnt;
__device__ unsigned g_epoch;

// ---------------- helpers ----------------
__device__ __forceinline__ unsigned long long pk2(float lo, float hi) {
    unsigned long long r;
    asm("mov.b64 %0, {%1,%2};" : "=l"(r) : "f"(lo), "f"(hi));
    return r;
}
__device__ __forceinline__ void upk2(unsigned long long v, float& lo, float& hi) {
    asm("mov.b64 {%0,%1}, %2;" : "=f"(lo), "=f"(hi) : "l"(v));
}
__device__ __forceinline__ void fma2(unsigned long long& d, unsigned long long a,
                                     unsigned long long b) {
    asm("fma.rn.f32x2 %0, %1, %2, %0;" : "+l"(d) : "l"(a), "l"(b));
}
__device__ __forceinline__ float sigf(float x) { return 1.0f / (1.0f + expf(-x)); }
__device__ __forceinline__ unsigned mono32(float f) {
    unsigned u = __float_as_uint(f);
    return (u & 0x80000000u) ? ~u : (u | 0x80000000u);
}
__device__ __forceinline__ uint32_t s2u(const void* p) {
    return (uint32_t)__cvta_generic_to_shared(p);
}
__device__ __forceinline__ void cp16(uint32_t dst, const void* src) {
    asm volatile("cp.async.ca.shared.global [%0], [%1], 16;" :: "r"(dst), "l"(src));
}
__device__ __forceinline__ void cp_commit() {
    asm volatile("cp.async.commit_group;");
}
template <int n>
__device__ __forceinline__ void cp_wait() {
    asm volatile("cp.async.wait_group %0;" :: "n"(n));
}
__device__ __forceinline__ unsigned ldcgu(const unsigned* p) {
    unsigned v;
    asm volatile("ld.global.cg.u32 %0, [%1];" : "=r"(v) : "l"(p));
    return v;
}

// ---------------- grid barrier (148 co-resident blocks) ----------------
__device__ __forceinline__ void gbar(unsigned target) {
    __threadfence();
    __syncthreads();
    if (threadIdx.x == 0) {
        unsigned old = atomicAdd(&g_cnt, 1u);
        if (old == 147u) {
            g_cnt = 0u;
            __threadfence();
            atomicAdd(&g_epoch, 1u);
        } else {
            while (ldcgu(&g_epoch) < target) __nanosleep(64);
        }
    }
    __syncthreads();
}

// ---------------- GEMM v5 (proven R5 core) ----------------
// C[32, 64-col tile] = A[32,K] @ W[K,N].  256 threads (8 warps).
// warp w -> rows 4w..4w+3 ; lane -> cols (col0, col0+1).
// A staged once into smem s_a[k*34 + r]; W via cp.async double-buffered 64-k chunks.
#define CHK 64
#define WBUF (CHK * 64)

__device__ __forceinline__ void fill_w(const float* __restrict__ W, int ldw,
                                       int bcol, int N, int k0, float* s_wbuf)
{
    int tid = threadIdx.x;
    int kk = tid >> 4;
    int c4 = (tid & 15) * 4;
    int col = bcol + c4;
#pragma unroll
    for (int p = 0; p < 4; p++) {
        int k = k0 + kk + p * 16;
        if (col < N)
            cp16(s2u(s_wbuf + (kk + p * 16) * 64 + c4),
                 W + (size_t)k * ldw + col);
    }
    cp_commit();
}

template <int K, class AElem>
__device__ __forceinline__ void gemm_v5(AElem aelem, const float* __restrict__ W,
    int ldw, int N, int bcol, unsigned long long acc[4], float* s_dyn)
{
    const int tid = threadIdx.x;
    const int lane = tid & 31;
    const int w = tid >> 5;
    float* s_w = s_dyn;                  // 2 * WBUF floats
    float* s_a = s_dyn + 2 * WBUF;       // K*34 floats
    constexpr int C = K / CHK;

    __syncthreads();                     // protect smem reuse across tiles
    fill_w(W, ldw, bcol, N, 0, s_w);
    if (C > 1) fill_w(W, ldw, bcol, N, CHK, s_w + WBUF);

#pragma unroll 1
    for (int r = 0; r < 32; r++) {
#pragma unroll
        for (int j = 0; j < K / 256; j++)
            s_a[(j * 256 + tid) * 34 + r] = aelem(r, j * 256 + tid);
        if (K % 256) {
            int k = (K / 256) * 256 + tid;
            if (k < K) s_a[k * 34 + r] = aelem(r, k);
        }
    }

    const float* sa = s_a + 4 * w;
#pragma unroll 1
    for (int c = 0; c < C; c++) {
        if (c + 1 < C) cp_wait<1>(); else cp_wait<0>();
        __syncthreads();
        const float* sw = s_w + (c & 1) * WBUF + 2 * lane;
        const float* sac = sa + c * CHK * 34;
#pragma unroll 16
        for (int kk = 0; kk < CHK; kk++) {
            float2 w2 = *(const float2*)(sw + kk * 64);
            float2 a01 = *(const float2*)(sac + kk * 34);
            float2 a23 = *(const float2*)(sac + kk * 34 + 2);
            unsigned long long wp = pk2(w2.x, w2.y);
            fma2(acc[0], wp, pk2(a01.x, a01.x));
            fma2(acc[1], wp, pk2(a01.y, a01.y));
            fma2(acc[2], wp, pk2(a23.x, a23.x));
            fma2(acc[3], wp, pk2(a23.y, a23.y));
        }
        if (c + 2 < C) {
            __syncthreads();
            fill_w(W, ldw, bcol, N, (c + 2) * CHK, s_w + (c & 1) * WBUF);
        }
    }
}

__device__ __forceinline__ void store_tile(unsigned long long acc[4],
    float* C, int ldc, int bcol, int N, const float* __restrict__ bias, int act)
{
    int lane = threadIdx.x & 31, w = threadIdx.x >> 5;
    int col0 = bcol + lane * 2;
    float b0 = 0.f, b1 = 0.f;
    if (bias) {
        if (col0 < N) b0 = bias[col0];
        if (col0 + 1 < N) b1 = bias[col0 + 1];
    }
#pragma unroll
    for (int r = 0; r < 4; r++) {
        int row = 4 * w + r;
        float a, b;
        upk2(acc[r], a, b);
        a += b0; b += b1;
        if (act == 1) { a = sigf(a); b = sigf(b); }
        if (col0 < N)     C[(size_t)row * ldc + col0] = a;
        if (col0 + 1 < N) C[(size_t)row * ldc + col0 + 1] = b;
    }
}

// ---------------- setup ----------------
__global__ void __launch_bounds__(256) k_encproj(const float* __restrict__ feat,
                                                 const float* __restrict__ W2,
                                                 const float* __restrict__ b2)
{
    extern __shared__ float s_dyn[];
    unsigned long long acc[4] = {0, 0, 0, 0};
    int bcol = blockIdx.x * 64;
    const float* A = feat + (size_t)blockIdx.y * 32 * FF;
    gemm_v5<FF>([&](int r, int k) { return A[(size_t)r * FF + k]; },
                W2, HH, HH, bcol, acc, s_dyn);
    store_tile(acc, g_encproj + (size_t)blockIdx.y * 32 * HH, HH, bcol, HH, b2, 0);
}

__global__ void __launch_bounds__(256) k_init(const float* __restrict__ feat,
                                              const float* __restrict__ Wh,
                                              const float* __restrict__ bh,
                                              const float* __restrict__ Wc,
                                              const float* __restrict__ bc)
{
    __shared__ float s_mean[FF];
    int b = blockIdx.x, tid = threadIdx.x;
    const float* fb = feat + (size_t)b * NN * FF;
    for (int f = tid; f < FF; f += 256) {
        float s = 0.f;
#pragma unroll 8
        for (int n = 0; n < NN; n++) s += fb[(size_t)n * FF + f];
        s_mean[f] = s * (1.0f / NN);
    }
    __syncthreads();
    for (int j = tid; j < HH; j += 256) {
        float ha = bh[j], ca = bc[j];
#pragma unroll 8
        for (int f = 0; f < FF; f++) {
            float m = s_mean[f];
            ha = fmaf(m, Wh[(size_t)f * HH + j], ha);
            ca = fmaf(m, Wc[(size_t)f * HH + j], ca);
        }
        g_h[0][b * HH + j] = ha;
        g_c[0][b * HH + j] = ca;
    }
    if (tid == 0) g_amax[b] = (unsigned long long)(0xFFFFFFFFu - 1u);  // SOS=1
    if (blockIdx.x == 0 && tid == 0) { g_cnt = 0u; g_epoch = 0u; }
}

// ---------------- persistent per-step tiles ----------------
// id 0..7: hq ; 8..27: gate ; 28..59: Whh->gpart1 ; 60..216: Wout logits(t-1)+argmax
__device__ __forceinline__ void tile_P1(int id, int t, int p,
    const float* __restrict__ W1, const float* __restrict__ b1,
    const float* __restrict__ Wg, const float* __restrict__ bg,
    const float* __restrict__ Whh,
    const float* __restrict__ Wout, const float* __restrict__ bout,
    float* __restrict__ out, float* s_dyn)
{
    unsigned long long acc[4] = {0, 0, 0, 0};
    if (id < 8) {
        int bcol = id * 64;
        gemm_v5<HH>([&](int r, int k) { return __ldcg(&g_h[p][r * HH + k]); },
                    W1, HH, HH, bcol, acc, s_dyn);
        store_tile(acc, g_hq, HH, bcol, HH, b1, 0);
    } else if (id < 28) {
        int bcol = (id - 8) * 64;
        gemm_v5<HH>([&](int r, int k) { return __ldcg(&g_h[p][r * HH + k]); },
                    Wg, FF, FF, bcol, acc, s_dyn);
        store_tile(acc, g_gate, FF, bcol, FF, bg, 1);
    } else if (id < 60) {
        int bcol = (id - 28) * 64;
        gemm_v5<HH>([&](int r, int k) { return __ldcg(&g_h[p][r * HH + k]); },
                    Whh, G4, G4, bcol, acc, s_dyn);
        store_tile(acc, g_gpart[1], G4, bcol, G4, nullptr, 0);
    } else if (t > 0) {
        int bcol = (id - 60) * 64;
        gemm_v5<HH>([&](int r, int k) { return __ldcg(&g_h[p][r * HH + k]); },
                    Wout, VV, VV, bcol, acc, s_dyn);
        int tt = t - 1;
        int lane = threadIdx.x & 31, w = threadIdx.x >> 5;
        int col0 = bcol + lane * 2;
        float b0 = (col0 < VV) ? bout[col0] : 0.f;
        float b1v = (col0 + 1 < VV) ? bout[col0 + 1] : 0.f;
#pragma unroll
        for (int r = 0; r < 4; r++) {
            int row = 4 * w + r;
            float a, b;
            upk2(acc[r], a, b);
            a += b0; b += b1v;
            unsigned long long best = 0ull;
            if (col0 < VV) {
                out[((size_t)row * TT + tt) * VV + col0] = a;
                best = ((unsigned long long)mono32(a) << 32) |
                       (0xFFFFFFFFu - (unsigned)col0);
            }
            if (col0 + 1 < VV) {
                out[((size_t)row * TT + tt) * VV + col0 + 1] = b;
                unsigned long long k1 = ((unsigned long long)mono32(b) << 32) |
                                        (0xFFFFFFFFu - (unsigned)(col0 + 1));
                if (k1 > best) best = k1;
            }
#pragma unroll
            for (int m = 16; m; m >>= 1) {
                unsigned long long o = __shfl_xor_sync(0xffffffffu, best, m);
                if (o > best) best = o;
            }
            if (lane == 0) atomicMax(&g_amax[row], best);
        }
    }
}

// ---------------- THE persistent kernel: all 80 steps ----------------
__global__ void __launch_bounds__(256) k_persist(
    const float* __restrict__ feat, const float* __restrict__ emb,
    const float* __restrict__ W1, const float* __restrict__ b1,
    const float* __restrict__ Wg, const float* __restrict__ bg,
    const float* __restrict__ Wx, const float* __restrict__ Whh,
    const float* __restrict__ blstm,
    const float* __restrict__ Wout, const float* __restrict__ bout,
    const float* __restrict__ Va, float* __restrict__ out)
{
    extern __shared__ float s_dyn[];
    __shared__ unsigned s_tok[32];
    const int bx = blockIdx.x, tid = threadIdx.x;
    const int lane = tid & 31;
    unsigned ep = 0;

    for (int t = 0; ; t++) {
        const int p = t & 1;
        // ---- Phase 1: 148 tiles ----
        tile_P1(bx, t, p, W1, b1, Wg, bg, Whh, Wout, bout, out, s_dyn);
        if (t == TT) {
            // finish remaining Wout tiles (ids 148..216); no barrier needed
            if (bx < 69)
                tile_P1(148 + bx, t, p, W1, b1, Wg, bg, Whh, Wout, bout, out, s_dyn);
            return;
        }
        gbar(++ep);

        // ---- Phase 2: remaining Wout tiles + Bahdanau scores ----
        if (bx < 69) {
            tile_P1(148 + bx, t, p, W1, b1, Wg, bg, Whh, Wout, bout, out, s_dyn);
        } else {
            int wg = (bx - 69) * 8 + (tid >> 5);
            for (int u = wg; u < BB * NN; u += 632) {
                int b = u >> 6, n = u & 63;
                const float4* ep4 = (const float4*)(g_encproj + ((size_t)b * NN + n) * HH);
                const float4* hq4 = (const float4*)(g_hq + (size_t)b * HH);
                const float4* va4 = (const float4*)Va;
                float s = 0.f;
#pragma unroll
                for (int i = 0; i < 4; i++) {
                    int e4 = lane + 32 * i;
                    float4 v = ep4[e4];
                    float4 h4 = __ldcg(hq4 + e4);
                    float4 a4 = va4[e4];
                    s += fmaxf(v.x + h4.x, 0.f) * a4.x;
                    s += fmaxf(v.y + h4.y, 0.f) * a4.y;
                    s += fmaxf(v.z + h4.z, 0.f) * a4.z;
                    s += fmaxf(v.w + h4.w, 0.f) * a4.w;
                }
#pragma unroll
                for (int m = 16; m; m >>= 1) s += __shfl_xor_sync(0xffffffffu, s, m);
                if (lane == 0) g_scor[b * NN + n] = s;
            }
        }
        gbar(++ep);

        // ---- Phase 3: gpart0 (token embed GEMM) + gated context ----
        if (bx < 32) {
            if (tid < 32)
                s_tok[tid] = 0xFFFFFFFFu -
                             (unsigned)(__ldcg(&g_amax[tid]) & 0xFFFFFFFFull);
            __syncthreads();
            unsigned long long acc[4] = {0, 0, 0, 0};
            int bcol = bx * 64;
            gemm_v5<EE>([&](int r, int k) { return emb[(size_t)s_tok[r] * EE + k]; },
                        Wx, G4, G4, bcol, acc, s_dyn);
            store_tile(acc, g_gpart[0], G4, bcol, G4, blstm, 0);
        } else {
            float* s_w = s_dyn;
            float* s_red = s_dyn + 64;
            for (int u = bx - 32; u < 160; u += 116) {
                int b = u / 5, fc = u - b * 5;
                __syncthreads();
                float v = 0.f;
                if (tid < 64) v = __ldcg(&g_scor[b * NN + tid]);
                float m = v;
#pragma unroll
                for (int s = 16; s; s >>= 1)
                    m = fmaxf(m, __shfl_xor_sync(0xffffffffu, m, s));
                if (tid < 64 && lane == 0) s_red[tid >> 5] = m;
                __syncthreads();
                if (tid < 64) {
                    float e = __expf(v - fmaxf(s_red[0], s_red[1]));
                    s_w[tid] = e;
                    float sum = e;
#pragma unroll
                    for (int s = 16; s; s >>= 1)
                        sum += __shfl_xor_sync(0xffffffffu, sum, s);
                    if (lane == 0) s_red[2 + (tid >> 5)] = sum;
                }
                __syncthreads();
                float inv = 1.0f / (s_red[2] + s_red[3]);
                int f = fc * 256 + tid;
                const float* fb = feat + (size_t)b * NN * FF + f;
                float a = 0.f;
#pragma unroll 16
                for (int n = 0; n < NN; n++) a += s_w[n] * fb[(size_t)n * FF];
                a *= inv;
                g_ctxg[b * FF + f] = a * __ldcg(&g_gate[b * FF + f]);
                if (fc == 0 && tid < 64)
                    out[OFF_ATT + ((size_t)b * TT + t) * NN + tid] = s_w[tid] * inv;
            }
        }
        gbar(++ep);

        // ---- Phase 4: g2 (4 K-slices of 320) ----
        if (bx < 128) {
            unsigned long long acc[4] = {0, 0, 0, 0};
            int ks = bx >> 5, bcol = (bx & 31) * 64;
            const float* Wp = Wx + (size_t)(EE + ks * 320) * G4;
            int koff = ks * 320;
            gemm_v5<320>([&](int r, int k) { return __ldcg(&g_ctxg[r * FF + koff + k]); },
                         Wp, G4, G4, bcol, acc, s_dyn);
            store_tile(acc, g_gpart[2 + ks], G4, bcol, G4, nullptr, 0);
        }
        gbar(++ep);

        // ---- Phase 5: LSTM pointwise + amax reset ----
        if (bx < 64) {
            int b = bx >> 1;
            int j = (bx & 1) * 256 + tid;
            float v[4];
#pragma unroll
            for (int g = 0; g < 4; g++) {
                float s = 0.f;
#pragma unroll
                for (int pt = 0; pt < 6; pt++)
                    s += __ldcg(&g_gpart[pt][b * G4 + g * HH + j]);
                v[g] = s;
            }
            float c_old = __ldcg(&g_c[p][b * HH + j]);
            float c2 = sigf(v[1]) * c_old + sigf(v[0]) * tanhf(v[2]);
            float h2 = sigf(v[3]) * tanhf(c2);
            g_c[p ^ 1][b * HH + j] = c2;
            g_h[p ^ 1][b * HH + j] = h2;
            if (t == TT - 1) {
                out[OFF_H + b * HH + j] = h2;
                out[OFF_C + b * HH + j] = c2;
            }
            if ((bx & 1) == 0 && tid == 0) g_amax[b] = 0ull;
        }
        gbar(++ep);
    }
}

// ---------------- launch ----------------
extern "C" void kernel_launch(void* const* d_in, const int* in_sizes, int n_in,
                              void* d_out, int out_size)
{
    int off = (n_in >= 21) ? 1 : 0;
    const float* feat  = (const float*)d_in[0];
    const float* emb   = (const float*)d_in[2 + off];
    const float* W1    = (const float*)d_in[3 + off];
    const float* b1    = (const float*)d_in[4 + off];
    const float* W2    = (const float*)d_in[5 + off];
    const float* b2    = (const float*)d_in[6 + off];
    const float* Va    = (const float*)d_in[7 + off];
    const float* Wh    = (const float*)d_in[9 + off];
    const float* bh    = (const float*)d_in[10 + off];
    const float* Wc    = (const float*)d_in[11 + off];
    const float* bc    = (const float*)d_in[12 + off];
    const float* Wg    = (const float*)d_in[13 + off];
    const float* bg    = (const float*)d_in[14 + off];
    const float* Wx    = (const float*)d_in[15 + off];
    const float* Whh   = (const float*)d_in[16 + off];
    const float* blstm = (const float*)d_in[17 + off];
    const float* Wout  = (const float*)d_in[18 + off];
    const float* bout  = (const float*)d_in[19 + off];
    float* out = (float*)d_out;

    const int SMW    = 2 * WBUF * 4;                 // 32768
    const int SM512  = SMW + HH * 34 * 4;            // 102400
    const int SM1280 = SMW + FF * 34 * 4;            // 206848
    cudaFuncSetAttribute(k_persist, cudaFuncAttributeMaxDynamicSharedMemorySize, SM512);
    cudaFuncSetAttribute(k_encproj, cudaFuncAttributeMaxDynamicSharedMemorySize, SM1280);

    k_init<<<BB, 256>>>(feat, Wh, bh, Wc, bc);
    k_encproj<<<dim3(HH / 64, (BB * NN) / 32), 256, SM1280>>>(feat, W2, b2);
    k_persist<<<148, 256, SM512>>>(feat, emb, W1, b1, Wg, bg, Wx, Whh, blstm,
                                   Wout, bout, Va, out);
}

// round 8
// speedup vs baseline: 1.7885x; 1.3236x over previous
#include <cuda_runtime.h>
#include <cuda_bf16.h>
#include <cstdint>

typedef unsigned long long ull;

#define BB 32
#define NN 64
#define FF 1280
#define HH 512
#define EE 512
#define VV 10000
#define TT 80
#define G4 2048
#define PAD 36
#define CHK 64

#define OFF_H   25600000ll
#define OFF_C   25616384ll
#define OFF_ATT 25632768ll

// ---------------- device state ----------------
__device__ float g_h[2][BB * HH];
__device__ float g_c[2][BB * HH];
__device__ float g_hq[BB * HH];
__device__ float g_gate[BB * FF];
__device__ float g_ctxg[BB * FF];
__device__ float g_scor[BB * NN];
__device__ float g_mean[BB * FF];
__device__ float g_encproj[BB * NN * HH];
__device__ float g_gpart[8][BB * G4];
__device__ ull g_amax[BB];
__device__ unsigned g_cnt;
__device__ unsigned g_epoch;

// ---------------- helpers ----------------
__device__ __forceinline__ ull pk2(float lo, float hi) {
    ull r;
    asm("mov.b64 %0, {%1,%2};" : "=l"(r) : "f"(lo), "f"(hi));
    return r;
}
__device__ __forceinline__ void upk2(ull v, float& lo, float& hi) {
    asm("mov.b64 {%0,%1}, %2;" : "=f"(lo), "=f"(hi) : "l"(v));
}
__device__ __forceinline__ void fma2(ull& d, ull a, ull b) {
    asm("fma.rn.f32x2 %0, %1, %2, %0;" : "+l"(d) : "l"(a), "l"(b));
}
__device__ __forceinline__ float sigf(float x) { return 1.0f / (1.0f + expf(-x)); }
__device__ __forceinline__ unsigned mono32(float f) {
    unsigned u = __float_as_uint(f);
    return (u & 0x80000000u) ? ~u : (u | 0x80000000u);
}
__device__ __forceinline__ uint32_t s2u(const void* p) {
    return (uint32_t)__cvta_generic_to_shared(p);
}
__device__ __forceinline__ void cp16(uint32_t dst, const void* src) {
    asm volatile("cp.async.ca.shared.global [%0], [%1], 16;" :: "r"(dst), "l"(src));
}
__device__ __forceinline__ void cp_commit() {
    asm volatile("cp.async.commit_group;");
}
template <int n>
__device__ __forceinline__ void cp_wait() {
    asm volatile("cp.async.wait_group %0;" :: "n"(n));
}
__device__ __forceinline__ unsigned ldcgu(const unsigned* p) {
    unsigned v;
    asm volatile("ld.global.cg.u32 %0, [%1];" : "=r"(v) : "l"(p));
    return v;
}

// ---------------- grid barrier (148 co-resident blocks) ----------------
__device__ __forceinline__ void gbar(unsigned target) {
    __threadfence();
    __syncthreads();
    if (threadIdx.x == 0) {
        unsigned old = atomicAdd(&g_cnt, 1u);
        if (old == 147u) {
            g_cnt = 0u;
            __threadfence();
            atomicAdd(&g_epoch, 1u);
        } else {
            while (ldcgu(&g_epoch) < target) __nanosleep(64);
        }
    }
    __syncthreads();
}

// ---------------- GEMM core (templated cols) ----------------
// C[32, COLS tile] = A[32,K] @ W[K,N].  256 threads (8 warps).
// warp wid -> rows 4wid..4wid+3 ; lane -> COLS/64 col-pairs at col0 = bcol + lane*2*(COLS/64).
// A staged in smem s_a[k*PAD + r] (one broadcast LDS.128 per warp-k).
// W via cp.async, double-buffered CHK-k chunks.
template <int COLS>
__device__ __forceinline__ void fill_w(const float* __restrict__ W, int ldw,
                                       int bcol, int N, int k0, float* s_wbuf)
{
    constexpr int GR = COLS / 4;     // thread groups per k-row
    constexpr int KSTEP = 256 / GR;  // k-rows per pass
    int tid = threadIdx.x;
    int kk = tid / GR;
    int c4 = (tid % GR) * 4;
    int col = bcol + c4;
#pragma unroll
    for (int p = 0; p < CHK / KSTEP; p++) {
        int kr = kk + p * KSTEP;
        if (col < N)
            cp16(s2u(s_wbuf + kr * COLS + c4), W + (size_t)(k0 + kr) * ldw + col);
    }
    cp_commit();
}

template <int K, int COLS, class AElem>
__device__ __forceinline__ void gemm(AElem aelem, const float* __restrict__ W,
    int ldw, int N, int bcol, ull* acc, float* s_dyn)
{
    constexpr int WB = CHK * COLS;
    constexpr int C = K / CHK;
    const int tid = threadIdx.x;
    const int lane = tid & 31;
    const int wid = tid >> 5;
    float* s_w = s_dyn;
    float* s_a = s_dyn + 2 * WB;

    __syncthreads();
    fill_w<COLS>(W, ldw, bcol, N, 0, s_w);
    if (C > 1) fill_w<COLS>(W, ldw, bcol, N, CHK, s_w + WB);

    // A staging: flat, MLP-8
#pragma unroll 8
    for (int idx = tid; idx < 32 * K; idx += 256) {
        int r = idx / K, k = idx - r * K;
        s_a[k * PAD + r] = aelem(r, k);
    }

    const float* sa0 = s_a + 4 * wid;
#pragma unroll 1
    for (int c = 0; c < C; c++) {
        if (c + 1 < C) cp_wait<1>(); else cp_wait<0>();
        __syncthreads();
        const float* sw = s_w + (c & 1) * WB + ((COLS == 128) ? 4 * lane : 2 * lane);
        const float* sac = sa0 + c * CHK * PAD;
#pragma unroll 16
        for (int kk = 0; kk < CHK; kk++) {
            float4 a4 = *(const float4*)(sac + kk * PAD);
            if (COLS == 128) {
                float4 w4 = *(const float4*)(sw + kk * COLS);
                ull wp0 = pk2(w4.x, w4.y), wp1 = pk2(w4.z, w4.w);
                fma2(acc[0], wp0, pk2(a4.x, a4.x)); fma2(acc[1], wp1, pk2(a4.x, a4.x));
                fma2(acc[2], wp0, pk2(a4.y, a4.y)); fma2(acc[3], wp1, pk2(a4.y, a4.y));
                fma2(acc[4], wp0, pk2(a4.z, a4.z)); fma2(acc[5], wp1, pk2(a4.z, a4.z));
                fma2(acc[6], wp0, pk2(a4.w, a4.w)); fma2(acc[7], wp1, pk2(a4.w, a4.w));
            } else {
                float2 w2 = *(const float2*)(sw + kk * COLS);
                ull wp = pk2(w2.x, w2.y);
                fma2(acc[0], wp, pk2(a4.x, a4.x));
                fma2(acc[1], wp, pk2(a4.y, a4.y));
                fma2(acc[2], wp, pk2(a4.z, a4.z));
                fma2(acc[3], wp, pk2(a4.w, a4.w));
            }
        }
        if (c + 2 < C) {
            __syncthreads();
            fill_w<COLS>(W, ldw, bcol, N, (c + 2) * CHK, s_w + (c & 1) * WB);
        }
    }
}

// acc layout: acc[r*CP + p] = f32x2 over cols (col0+2p, col0+2p+1), row 4*wid+r.
template <int COLS>
__device__ __forceinline__ void store_tile(ull* acc, float* C, int ldc,
    int bcol, int N, const float* __restrict__ bias, int act)
{
    constexpr int CP = COLS / 64;
    int lane = threadIdx.x & 31, wid = threadIdx.x >> 5;
    int col0 = bcol + lane * 2 * CP;
    float bb[2 * CP];
#pragma unroll
    for (int q = 0; q < 2 * CP; q++)
        bb[q] = (bias && col0 + q < N) ? bias[col0 + q] : 0.f;
#pragma unroll
    for (int r = 0; r < 4; r++) {
        int row = 4 * wid + r;
#pragma unroll
        for (int p = 0; p < CP; p++) {
            float x0, x1;
            upk2(acc[r * CP + p], x0, x1);
            int ce = col0 + 2 * p, co = ce + 1;
            x0 += bb[2 * p]; x1 += bb[2 * p + 1];
            if (act == 1) { x0 = sigf(x0); x1 = sigf(x1); }
            if (ce < N) C[(size_t)row * ldc + ce] = x0;
            if (co < N) C[(size_t)row * ldc + co] = x1;
        }
    }
}

// ---------------- setup kernels ----------------
__global__ void __launch_bounds__(256) k_mean(const float* __restrict__ feat)
{
    int b = blockIdx.x, tid = threadIdx.x;
    const float* fb = feat + (size_t)b * NN * FF;
#pragma unroll
    for (int i = 0; i < FF / 256; i++) {
        int f = i * 256 + tid;
        float s = 0.f;
#pragma unroll 8
        for (int n = 0; n < NN; n++) s += fb[(size_t)n * FF + f];
        g_mean[b * FF + f] = s * (1.0f / NN);
    }
    if (tid == 0) g_amax[b] = (ull)(0xFFFFFFFFu - 1u);   // token = SOS = 1
    if (b == 0 && tid == 0) { g_cnt = 0u; g_epoch = 0u; }
}

__global__ void __launch_bounds__(256) k_hc0(const float* __restrict__ Wh,
                                             const float* __restrict__ bh,
                                             const float* __restrict__ Wc,
                                             const float* __restrict__ bc)
{
    extern __shared__ float s_dyn[];
    ull acc[4] = {0, 0, 0, 0};
    int id = blockIdx.x;
    auto A = [&](int r, int k) { return g_mean[r * FF + k]; };
    if (id < 8) {
        int bcol = id * 64;
        gemm<FF, 64>(A, Wh, HH, HH, bcol, acc, s_dyn);
        store_tile<64>(acc, g_h[0], HH, bcol, HH, bh, 0);
    } else {
        int bcol = (id - 8) * 64;
        gemm<FF, 64>(A, Wc, HH, HH, bcol, acc, s_dyn);
        store_tile<64>(acc, g_c[0], HH, bcol, HH, bc, 0);
    }
}

__global__ void __launch_bounds__(256) k_encproj(const float* __restrict__ feat,
                                                 const float* __restrict__ W2,
                                                 const float* __restrict__ b2)
{
    extern __shared__ float s_dyn[];
    ull acc[4] = {0, 0, 0, 0};
    int bcol = blockIdx.x * 64;
    const float* A = feat + (size_t)blockIdx.y * 32 * FF;
    gemm<FF, 64>([&](int r, int k) { return A[(size_t)r * FF + k]; },
                 W2, HH, HH, bcol, acc, s_dyn);
    store_tile<64>(acc, g_encproj + (size_t)blockIdx.y * 32 * HH, HH, bcol, HH, b2, 0);
}

// ---------------- P1 tiles (all h(t)-dependent GEMMs) ----------------
// id 0..3: hq ; 4..13: gate ; 14..29: Whh->gpart2 ; 30..108: Wout logits(t-1)+argmax
__device__ __forceinline__ void phase1(int id, int t, int p,
    const float* __restrict__ W1, const float* __restrict__ b1,
    const float* __restrict__ Wg, const float* __restrict__ bg,
    const float* __restrict__ Whh,
    const float* __restrict__ Wout, const float* __restrict__ bout,
    float* __restrict__ out, float* s_dyn)
{
    ull acc[8] = {0, 0, 0, 0, 0, 0, 0, 0};
    auto hA = [&](int r, int k) { return __ldcg(&g_h[p][r * HH + k]); };
    if (id < 4) {
        int bcol = id * 128;
        gemm<HH, 128>(hA, W1, HH, HH, bcol, acc, s_dyn);
        store_tile<128>(acc, g_hq, HH, bcol, HH, b1, 0);
    } else if (id < 14) {
        int bcol = (id - 4) * 128;
        gemm<HH, 128>(hA, Wg, FF, FF, bcol, acc, s_dyn);
        store_tile<128>(acc, g_gate, FF, bcol, FF, bg, 1);
    } else if (id < 30) {
        int bcol = (id - 14) * 128;
        gemm<HH, 128>(hA, Whh, G4, G4, bcol, acc, s_dyn);
        store_tile<128>(acc, g_gpart[2], G4, bcol, G4, nullptr, 0);
    } else if (id < 109 && t > 0) {
        int bcol = (id - 30) * 128;
        gemm<HH, 128>(hA, Wout, VV, VV, bcol, acc, s_dyn);
        int tt = t - 1;
        int lane = threadIdx.x & 31, wid = threadIdx.x >> 5;
        int col0 = bcol + lane * 4;
#pragma unroll
        for (int r = 0; r < 4; r++) {
            int row = 4 * wid + r;
            ull best = 0ull;
#pragma unroll
            for (int p2 = 0; p2 < 2; p2++) {
                float x0, x1;
                upk2(acc[r * 2 + p2], x0, x1);
                int ce = col0 + 2 * p2;
#pragma unroll
                for (int q = 0; q < 2; q++) {
                    int cc = ce + q;
                    if (cc < VV) {
                        float v = ((q == 0) ? x0 : x1) + bout[cc];
                        out[((size_t)row * TT + tt) * VV + cc] = v;
                        ull kkey = ((ull)mono32(v) << 32) |
                                   (0xFFFFFFFFu - (unsigned)cc);
                        if (kkey > best) best = kkey;
                    }
                }
            }
#pragma unroll
            for (int m = 16; m; m >>= 1) {
                ull o = __shfl_xor_sync(0xffffffffu, best, m);
                if (o > best) best = o;
            }
            if (lane == 0) atomicMax(&g_amax[row], best);
        }
    }
}

// ---------------- THE persistent kernel ----------------
__global__ void __launch_bounds__(256) k_persist(
    const float* __restrict__ feat, const float* __restrict__ emb,
    const float* __restrict__ W1, const float* __restrict__ b1,
    const float* __restrict__ Wg, const float* __restrict__ bg,
    const float* __restrict__ Wx, const float* __restrict__ Whh,
    const float* __restrict__ blstm,
    const float* __restrict__ Wout, const float* __restrict__ bout,
    const float* __restrict__ Va, float* __restrict__ out)
{
    extern __shared__ float s_dyn[];
    __shared__ unsigned s_tok[32];
    __shared__ float s_sm[NN + 8];
    const int bx = blockIdx.x, tid = threadIdx.x;
    const int lane = tid & 31, wid = tid >> 5;
    unsigned ep = 0;

    for (int t = 0; ; t++) {
        const int p = t & 1;
        // ---- Phase 1: 109 tiles — hq, gate, Whh, logits(t-1)+argmax ----
        phase1(bx, t, p, W1, b1, Wg, bg, Whh, Wout, bout, out, s_dyn);
        if (t == TT) return;
        gbar(++ep);

        // ---- Phase 2: gpart0/1 (token embed, 2 k-halves) + scores ----
        if (bx < 32) {
            if (tid < 32)
                s_tok[tid] = 0xFFFFFFFFu -
                             (unsigned)(__ldcg(&g_amax[tid]) & 0xFFFFFFFFull);
            __syncthreads();
            ull acc[8] = {0, 0, 0, 0, 0, 0, 0, 0};
            int half = bx >> 4, bcol = (bx & 15) * 128;
            int koff = half * 256;
            gemm<256, 128>([&](int r, int k)
                           { return emb[(size_t)s_tok[r] * EE + koff + k]; },
                           Wx + (size_t)koff * G4, G4, G4, bcol, acc, s_dyn);
            store_tile<128>(acc, g_gpart[half], G4, bcol, G4,
                            half == 0 ? blstm : nullptr, 0);
        } else {
            for (int u = (bx - 32) * 8 + wid; u < BB * NN; u += 928) {
                int b = u >> 6, n = u & 63;
                const float4* ep4 = (const float4*)(g_encproj + ((size_t)b * NN + n) * HH);
                const float4* hq4 = (const float4*)(g_hq + (size_t)b * HH);
                const float4* va4 = (const float4*)Va;
                float s = 0.f;
#pragma unroll
                for (int i = 0; i < 4; i++) {
                    int e4 = lane + 32 * i;
                    float4 v = ep4[e4];
                    float4 h4 = __ldcg(hq4 + e4);
                    float4 a4 = va4[e4];
                    s += fmaxf(v.x + h4.x, 0.f) * a4.x;
                    s += fmaxf(v.y + h4.y, 0.f) * a4.y;
                    s += fmaxf(v.z + h4.z, 0.f) * a4.z;
                    s += fmaxf(v.w + h4.w, 0.f) * a4.w;
                }
#pragma unroll
                for (int m = 16; m; m >>= 1) s += __shfl_xor_sync(0xffffffffu, s, m);
                if (lane == 0) g_scor[b * NN + n] = s;
            }
        }
        gbar(++ep);

        // ---- Phase 3: softmax (redundant per block) + gated context ----
        {
            float* s_w = s_sm;
            float* s_red = s_sm + NN;
            for (int u = bx; u < 160; u += 148) {
                int b = u / 5, fc = u - b * 5;
                __syncthreads();
                float v = 0.f;
                if (tid < 64) v = __ldcg(&g_scor[b * NN + tid]);
                float m = v;
#pragma unroll
                for (int s = 16; s; s >>= 1)
                    m = fmaxf(m, __shfl_xor_sync(0xffffffffu, m, s));
                if (tid < 64 && lane == 0) s_red[tid >> 5] = m;
                __syncthreads();
                if (tid < 64) {
                    float e = __expf(v - fmaxf(s_red[0], s_red[1]));
                    s_w[tid] = e;
                    float sum = e;
#pragma unroll
                    for (int s = 16; s; s >>= 1)
                        sum += __shfl_xor_sync(0xffffffffu, sum, s);
                    if (lane == 0) s_red[2 + (tid >> 5)] = sum;
                }
                __syncthreads();
                float inv = 1.0f / (s_red[2] + s_red[3]);
                int f = fc * 256 + tid;
                const float* fb = feat + (size_t)b * NN * FF + f;
                float a = 0.f;
#pragma unroll 16
                for (int n = 0; n < NN; n++) a += s_w[n] * fb[(size_t)n * FF];
                a *= inv;
                g_ctxg[b * FF + f] = a * __ldcg(&g_gate[b * FF + f]);
                if (fc == 0 && tid < 64)
                    out[OFF_ATT + ((size_t)b * TT + t) * NN + tid] = s_w[tid] * inv;
            }
        }
        gbar(++ep);

        // ---- Phase 4: Wx-bottom, 5 k-slices of 256 x 16 col tiles ----
        if (bx < 80) {
            ull acc[8] = {0, 0, 0, 0, 0, 0, 0, 0};
            int ks = bx >> 4, bcol = (bx & 15) * 128;
            int koff = ks * 256;
            gemm<256, 128>([&](int r, int k)
                           { return __ldcg(&g_ctxg[r * FF + koff + k]); },
                           Wx + (size_t)(EE + koff) * G4, G4, G4, bcol, acc, s_dyn);
            store_tile<128>(acc, g_gpart[3 + ks], G4, bcol, G4, nullptr, 0);
        }
        gbar(++ep);

        // ---- Phase 5: LSTM pointwise + amax reset ----
        if (bx < 64) {
            int b = bx >> 1;
            int j = (bx & 1) * 256 + tid;
            float v[4];
#pragma unroll
            for (int g = 0; g < 4; g++) {
                float s = 0.f;
#pragma unroll
                for (int pt = 0; pt < 8; pt++)
                    s += __ldcg(&g_gpart[pt][b * G4 + g * HH + j]);
                v[g] = s;
            }
            float c_old = __ldcg(&g_c[p][b * HH + j]);
            float c2 = sigf(v[1]) * c_old + sigf(v[0]) * tanhf(v[2]);
            float h2 = sigf(v[3]) * tanhf(c2);
            g_c[p ^ 1][b * HH + j] = c2;
            g_h[p ^ 1][b * HH + j] = h2;
            if (t == TT - 1) {
                out[OFF_H + b * HH + j] = h2;
                out[OFF_C + b * HH + j] = c2;
            }
            if ((bx & 1) == 0 && tid == 0) g_amax[b] = 0ull;
        }
        gbar(++ep);
    }
}

// ---------------- launch ----------------
extern "C" void kernel_launch(void* const* d_in, const int* in_sizes, int n_in,
                              void* d_out, int out_size)
{
    int off = (n_in >= 21) ? 1 : 0;
    const float* feat  = (const float*)d_in[0];
    const float* emb   = (const float*)d_in[2 + off];
    const float* W1    = (const float*)d_in[3 + off];
    const float* b1    = (const float*)d_in[4 + off];
    const float* W2    = (const float*)d_in[5 + off];
    const float* b2    = (const float*)d_in[6 + off];
    const float* Va    = (const float*)d_in[7 + off];
    const float* Wh    = (const float*)d_in[9 + off];
    const float* bh    = (const float*)d_in[10 + off];
    const float* Wc    = (const float*)d_in[11 + off];
    const float* bc    = (const float*)d_in[12 + off];
    const float* Wg    = (const float*)d_in[13 + off];
    const float* bg    = (const float*)d_in[14 + off];
    const float* Wx    = (const float*)d_in[15 + off];
    const float* Whh   = (const float*)d_in[16 + off];
    const float* blstm = (const float*)d_in[17 + off];
    const float* Wout  = (const float*)d_in[18 + off];
    const float* bout  = (const float*)d_in[19 + off];
    float* out = (float*)d_out;

    const int SMP = 2 * CHK * 128 * 4 + HH * PAD * 4;   // 65536 + 73728 = 139264
    const int SMB = 2 * CHK * 64 * 4 + FF * PAD * 4;    // 32768 + 184320 = 217088
    cudaFuncSetAttribute(k_persist, cudaFuncAttributeMaxDynamicSharedMemorySize, SMP);
    cudaFuncSetAttribute(k_encproj, cudaFuncAttributeMaxDynamicSharedMemorySize, SMB);
    cudaFuncSetAttribute(k_hc0, cudaFuncAttributeMaxDynamicSharedMemorySize, SMB);

    k_mean<<<BB, 256>>>(feat);
    k_hc0<<<16, 256, SMB>>>(Wh, bh, Wc, bc);
    k_encproj<<<dim3(HH / 64, (BB * NN) / 32), 256, SMB>>>(feat, W2, b2);
    k_persist<<<148, 256, SMP>>>(feat, emb, W1, b1, Wg, bg, Wx, Whh, blstm,
                                 Wout, bout, Va, out);
}